// round 15
// baseline (speedup 1.0000x reference)
#include <cuda_runtime.h>
#include <cuda_fp16.h>
#include <cuda_bf16.h>
#include <cstdint>

// Problem constants
#define IN_F    4096
#define OUT_F   11008
#define M_ROWS  4096
#define NGROUPS 32

// Scratch (no cudaMalloc allowed)
__device__ __half g_Xh[(size_t)M_ROWS * IN_F];    // fp16 x
__device__ __half g_Wh[(size_t)OUT_F * IN_F];     // fp16 dequant W, [n][k]
__device__ int    g_bad_f16;
__device__ int    g_bad_bf16;

// ---------------------------------------------------------------------------
// scales dtype probe (unchanged from passing rounds)
// ---------------------------------------------------------------------------
__global__ void probe_init() { g_bad_f16 = 0; g_bad_bf16 = 0; }

__global__ void probe_kernel(const void* __restrict__ scales) {
    int i = blockIdx.x * blockDim.x + threadIdx.x;
    if (i >= 176128) return;
    float vf = __half2float(((const __half*)scales)[i]);
    if (!(vf >= 0.0f && vf < 1.0f)) atomicExch(&g_bad_f16, 1);
    float vb = __bfloat162float(((const __nv_bfloat16*)scales)[i]);
    if (!(vb >= 0.0f && vb < 1.0f)) atomicExch(&g_bad_bf16, 1);
}

// Inline scale fetch: identical numerics to the old cvt_scales + __float2half
// round-trip (half path is an exact identity; bf16/f32 paths round once in
// the same place).
__device__ __forceinline__ __half load_scale(const void* scales, int idx) {
    if (!g_bad_f16)       return ((const __half*)scales)[idx];
    else if (!g_bad_bf16) return __float2half(
                              __bfloat162float(((const __nv_bfloat16*)scales)[idx]));
    else                  return __float2half(((const float*)scales)[idx]);
}

// ---------------------------------------------------------------------------
// Fused pre-pass: blocks [0, 8192) convert x -> g_Xh (fp16);
// blocks [8192, 13696) dequant qweight -> g_Wh with coalesced reads
// (tile 32 qrows x 32 n, lanes index n, smem transpose, contiguous writes).
// Dequant arithmetic bit-identical to the validated kernel.
// ---------------------------------------------------------------------------
__global__ __launch_bounds__(256) void prep_kernel(
    const float* __restrict__ x,
    const int* __restrict__ qweight, const int* __restrict__ qzeros,
    const void* __restrict__ scales)
{
    __shared__ __align__(16) uint4 ts[32 * 33];   // [qrow_local][n_local], pad 33

    const int bid = blockIdx.x;
    if (bid < 8192) {
        // ---- cvt path: 8 fp32 -> 8 fp16 per thread ----
        int idx = (bid * 256 + threadIdx.x) * 8;
        float4 f0 = *reinterpret_cast<const float4*>(x + idx);
        float4 f1 = *reinterpret_cast<const float4*>(x + idx + 4);
        __align__(16) __half2 h[4];
        h[0] = __floats2half2_rn(f0.x, f0.y);
        h[1] = __floats2half2_rn(f0.z, f0.w);
        h[2] = __floats2half2_rn(f1.x, f1.y);
        h[3] = __floats2half2_rn(f1.z, f1.w);
        *reinterpret_cast<uint4*>(g_Xh + idx) = *reinterpret_cast<const uint4*>(h);
    } else {
        const int r  = bid - 8192;            // 0..5503
        const int bx = r & 15;                // qrow block: 16 x 32 qrows
        const int by = r >> 4;                // n block: 344 x 32 n
        const int tx = threadIdx.x & 31;      // n_local
        const int ty = threadIdx.x >> 5;      // 0..7 (4 qrows each)
        const int n  = by * 32 + tx;
        const int g  = bx * 2 + (ty >> 2);    // group: qrows ty*4..ty*4+3 share it

        const int z = (qzeros[g * (OUT_F / 8) + (n >> 3)] >> ((n & 7) * 4)) & 15;
        const __half2 s2  = __half2half2(load_scale(scales, g * OUT_F + n));
        const __half2 mz2 = __half2half2(__float2half((float)(1024 + z)));

        // Phase 1: coalesced reads (lanes = consecutive n), dequant, stage
        #pragma unroll
        for (int i = 0; i < 4; i++) {
            const int qrl = ty * 4 + i;                       // qrow_local
            const uint32_t q = (uint32_t)qweight[(size_t)(bx * 32 + qrl) * OUT_F + n];
            uint32_t t0 = ( q         & 0x000F000Fu) | 0x64006400u;
            uint32_t t1 = ((q >> 4)   & 0x000F000Fu) | 0x64006400u;
            uint32_t t2 = ((q >> 8)   & 0x000F000Fu) | 0x64006400u;
            uint32_t t3 = ((q >> 12)  & 0x000F000Fu) | 0x64006400u;
            __half2 p0 = __hmul2(__hsub2(*(__half2*)&t0, mz2), s2);
            __half2 p1 = __hmul2(__hsub2(*(__half2*)&t1, mz2), s2);
            __half2 p2 = __hmul2(__hsub2(*(__half2*)&t2, mz2), s2);
            __half2 p3 = __hmul2(__hsub2(*(__half2*)&t3, mz2), s2);
            uint32_t u0 = *(uint32_t*)&p0, u1 = *(uint32_t*)&p1;
            uint32_t u2 = *(uint32_t*)&p2, u3 = *(uint32_t*)&p3;
            uint4 o;
            o.x = __byte_perm(u0, u1, 0x5410);
            o.y = __byte_perm(u2, u3, 0x5410);
            o.z = __byte_perm(u0, u1, 0x7632);
            o.w = __byte_perm(u2, u3, 0x7632);
            ts[qrl * 33 + tx] = o;
        }
        __syncthreads();

        // Phase 2: per-warp contiguous 512B writes. lane = qrow_local,
        // warp ty covers n_local = ty, ty+8, ty+16, ty+24.
        uint4* W = reinterpret_cast<uint4*>(g_Wh);
        #pragma unroll
        for (int j = 0; j < 4; j++) {
            const int nl = ty + j * 8;
            const int ng = by * 32 + nl;
            W[(size_t)ng * (IN_F / 8) + bx * 32 + tx] = ts[tx * 33 + nl];
        }
    }
}

// ---------------------------------------------------------------------------
// HGEMM (mma.sync) — EXACT round-14 best kernel. CTA 128x128, 4 warps
// (2m x 2n), warp tile 64x64, BK=64, 3-stage cp.async, 96KB smem ->
// 2 CTAs/SM. 128B rows, canonical SW128 swizzle (ch ^= row&7).
// ---------------------------------------------------------------------------
constexpr int BM  = 128;
constexpr int BN  = 128;
constexpr int BK  = 64;                   // halves
constexpr int STG = 3;
constexpr int NIT = IN_F / BK;            // 64
constexpr int A_BYTES = BM * BK * 2;      // 16KB
constexpr int B_BYTES = BN * BK * 2;      // 16KB
constexpr int STAGE_BYTES = A_BYTES + B_BYTES;          // 32KB
constexpr int GEMM_SMEM = STG * STAGE_BYTES;            // 96KB

__device__ __forceinline__ uint32_t smem_u32(const void* p) {
    uint32_t a;
    asm("{ .reg .u64 t; cvta.to.shared.u64 t, %1; cvt.u32.u64 %0, t; }"
        : "=r"(a) : "l"(p));
    return a;
}
// byte offset of (row, 16B chunk ch in 0..7) within a tile: 128B rows, SW128
__device__ __forceinline__ uint32_t sw_byte(int row, int ch) {
    return (uint32_t)((row << 7) + ((ch ^ (row & 7)) << 4));
}

__global__ __launch_bounds__(128, 2) void gemm_kernel(
    const float* __restrict__ bias, float* __restrict__ out)
{
    extern __shared__ char smem[];
    const uint32_t sbase = smem_u32(smem);

    const int tid  = threadIdx.x;
    const int lane = tid & 31;
    const int warp = tid >> 5;        // 0..3
    const int warp_m = warp & 1;      // 2 m-warps
    const int warp_n = warp >> 1;     // 2 n-warps

    // grid: m fastest -> A (32MB) stays L2 resident across n-bands
    const int pid_m = blockIdx.x & 31;       // 32
    const int pid_n = blockIdx.x >> 5;       // 86
    const int m_base = pid_m * BM;
    const int n_base = pid_n * BN;

    float acc[4][8][4];
    #pragma unroll
    for (int mi = 0; mi < 4; mi++)
        #pragma unroll
        for (int ni = 0; ni < 8; ni++)
            #pragma unroll
            for (int r = 0; r < 4; r++) acc[mi][ni][r] = 0.f;

    // producer: 2048 16B copies (A 1024, B 1024), 16 per thread
    auto produce = [&](int cc) {
        const uint32_t st = sbase + (cc % STG) * STAGE_BYTES;
        const int k0 = cc * BK;
        #pragma unroll
        for (int i = 0; i < 16; i++) {
            int id = tid + i * 128;           // 0..2047
            if (id < 1024) {
                int row = id >> 3, ch = id & 7;
                const __half* src = g_Xh + (size_t)(m_base + row) * IN_F + k0 + ch * 8;
                asm volatile("cp.async.cg.shared.global [%0], [%1], 16;\n"
                             :: "r"(st + sw_byte(row, ch)), "l"(src));
            } else {
                int idb = id - 1024;
                int row = idb >> 3, ch = idb & 7;
                const __half* src = g_Wh + (size_t)(n_base + row) * IN_F + k0 + ch * 8;
                asm volatile("cp.async.cg.shared.global [%0], [%1], 16;\n"
                             :: "r"(st + A_BYTES + sw_byte(row, ch)), "l"(src));
            }
        }
        asm volatile("cp.async.commit_group;\n");
    };

    auto compute = [&](int cc) {
        const uint32_t st = sbase + (cc % STG) * STAGE_BYTES;
        #pragma unroll
        for (int ks = 0; ks < 4; ks++) {      // 4 k16 sub-steps
            const int kc = ks * 2;
            uint32_t a[4][4], b[8][2];
            #pragma unroll
            for (int mi = 0; mi < 4; mi++) {
                int row = warp_m * 64 + mi * 16 + (lane & 15);
                int ch  = kc + (lane >> 4);
                uint32_t addr = st + sw_byte(row, ch);
                asm volatile(
                    "ldmatrix.sync.aligned.m8n8.x4.shared.b16 {%0,%1,%2,%3}, [%4];"
                    : "=r"(a[mi][0]), "=r"(a[mi][1]), "=r"(a[mi][2]), "=r"(a[mi][3])
                    : "r"(addr));
            }
            #pragma unroll
            for (int nt = 0; nt < 4; nt++) {  // x4 covers two n8 tiles
                int row = warp_n * 64 + nt * 16 + ((lane >> 4) << 3) + (lane & 7);
                int ch  = kc + ((lane >> 3) & 1);
                uint32_t addr = st + A_BYTES + sw_byte(row, ch);
                asm volatile(
                    "ldmatrix.sync.aligned.m8n8.x4.shared.b16 {%0,%1,%2,%3}, [%4];"
                    : "=r"(b[2*nt][0]), "=r"(b[2*nt][1]),
                      "=r"(b[2*nt+1][0]), "=r"(b[2*nt+1][1])
                    : "r"(addr));
            }
            #pragma unroll
            for (int mi = 0; mi < 4; mi++)
                #pragma unroll
                for (int ni = 0; ni < 8; ni++)
                    asm volatile(
                        "mma.sync.aligned.m16n8k16.row.col.f32.f16.f16.f32 "
                        "{%0,%1,%2,%3}, {%4,%5,%6,%7}, {%8,%9}, {%0,%1,%2,%3};"
                        : "+f"(acc[mi][ni][0]), "+f"(acc[mi][ni][1]),
                          "+f"(acc[mi][ni][2]), "+f"(acc[mi][ni][3])
                        : "r"(a[mi][0]), "r"(a[mi][1]), "r"(a[mi][2]), "r"(a[mi][3]),
                          "r"(b[ni][0]), "r"(b[ni][1]));
        }
    };

    // prologue: stages 0,1 in flight
    produce(0);
    produce(1);

    for (int c = 0; c < NIT; c++) {
        asm volatile("cp.async.wait_group 1;\n");        // group c complete
        __syncthreads();                                 // compute(c-1) done
        if (c + 2 < NIT) produce(c + 2);                 // stage (c+2)%3 == (c-1)%3: safe
        else asm volatile("cp.async.commit_group;\n");   // uniform group count
        compute(c);
    }

    // epilogue
    #pragma unroll
    for (int mi = 0; mi < 4; mi++) {
        int row0 = m_base + warp_m * 64 + mi * 16 + (lane >> 2);
        #pragma unroll
        for (int ni = 0; ni < 8; ni++) {
            int col = n_base + warp_n * 64 + ni * 8 + ((lane & 3) << 1);
            float b0 = bias[col], b1 = bias[col + 1];
            float2 v0 = make_float2(acc[mi][ni][0] + b0, acc[mi][ni][1] + b1);
            float2 v1 = make_float2(acc[mi][ni][2] + b0, acc[mi][ni][3] + b1);
            *reinterpret_cast<float2*>(out + (size_t)row0 * OUT_F + col)       = v0;
            *reinterpret_cast<float2*>(out + (size_t)(row0 + 8) * OUT_F + col) = v1;
        }
    }
}

// ---------------------------------------------------------------------------
extern "C" void kernel_launch(void* const* d_in, const int* in_sizes, int n_in,
                              void* d_out, int out_size)
{
    const void *p_x = nullptr, *p_qw = nullptr, *p_qz = nullptr,
               *p_sc = nullptr, *p_b = nullptr;
    for (int i = 0; i < n_in; i++) {
        switch (in_sizes[i]) {
            case M_ROWS * IN_F:        p_x  = d_in[i]; break;
            case (IN_F / 8) * OUT_F:   p_qw = d_in[i]; break;
            case NGROUPS * (OUT_F/8):  p_qz = d_in[i]; break;
            case NGROUPS * OUT_F:      p_sc = d_in[i]; break;
            case OUT_F:                p_b  = d_in[i]; break;
        }
    }

    probe_init<<<1, 1>>>();
    probe_kernel<<<(176128 + 255) / 256, 256>>>(p_sc);

    // fused pre-pass: 8192 cvt blocks + 5504 dequant blocks (16 x 344 tiles);
    // scale dtype conversion is inlined in the dequant path (flags from probe)
    prep_kernel<<<8192 + 5504, 256>>>((const float*)p_x,
                                      (const int*)p_qw, (const int*)p_qz, p_sc);

    // Not stream-ordered; safe and deterministic on every call (incl. capture).
    cudaFuncSetAttribute(gemm_kernel,
                         cudaFuncAttributeMaxDynamicSharedMemorySize, GEMM_SMEM);

    // grid: 32 m-tiles x 86 n-tiles, m fastest
    gemm_kernel<<<32 * 86, 128, GEMM_SMEM>>>((const float*)p_b, (float*)d_out);
}

// round 16
// speedup vs baseline: 1.0665x; 1.0665x over previous
#include <cuda_runtime.h>
#include <cuda_fp16.h>
#include <cuda_bf16.h>
#include <cstdint>

// Problem constants
#define IN_F    4096
#define OUT_F   11008
#define M_ROWS  4096
#define NGROUPS 32

// Scratch (no cudaMalloc allowed)
__device__ __half g_Xh[(size_t)M_ROWS * IN_F];    // fp16 x
__device__ __half g_Wh[(size_t)OUT_F * IN_F];     // fp16 dequant W, [n][k]
__device__ int    g_bad_f16;
__device__ int    g_bad_bf16;

// ---------------------------------------------------------------------------
// scales dtype probe (unchanged from passing rounds)
// ---------------------------------------------------------------------------
__global__ void probe_init() { g_bad_f16 = 0; g_bad_bf16 = 0; }

__global__ void probe_kernel(const void* __restrict__ scales) {
    int i = blockIdx.x * blockDim.x + threadIdx.x;
    if (i >= 176128) return;
    float vf = __half2float(((const __half*)scales)[i]);
    if (!(vf >= 0.0f && vf < 1.0f)) atomicExch(&g_bad_f16, 1);
    float vb = __bfloat162float(((const __nv_bfloat16*)scales)[i]);
    if (!(vb >= 0.0f && vb < 1.0f)) atomicExch(&g_bad_bf16, 1);
}

__device__ __forceinline__ __half load_scale(const void* scales, int idx) {
    if (!g_bad_f16)       return ((const __half*)scales)[idx];
    else if (!g_bad_bf16) return __float2half(
                              __bfloat162float(((const __nv_bfloat16*)scales)[idx]));
    else                  return __float2half(((const float*)scales)[idx]);
}

// ---------------------------------------------------------------------------
// Fused pre-pass:
//   blocks [0, 8192):        x fp32 -> g_Xh fp16
//   blocks [8192, 13696):    dequant qweight -> g_Wh (coalesced transpose)
//   blocks [13696, 15232):   zero out[:, 10624:] (split-K tail accum region)
// ---------------------------------------------------------------------------
__global__ __launch_bounds__(256) void prep_kernel(
    const float* __restrict__ x,
    const int* __restrict__ qweight, const int* __restrict__ qzeros,
    const void* __restrict__ scales, float* __restrict__ out)
{
    __shared__ __align__(16) uint4 ts[32 * 33];   // [qrow_local][n_local], pad 33

    const int bid = blockIdx.x;
    if (bid < 8192) {
        // ---- cvt path: 8 fp32 -> 8 fp16 per thread ----
        int idx = (bid * 256 + threadIdx.x) * 8;
        float4 f0 = *reinterpret_cast<const float4*>(x + idx);
        float4 f1 = *reinterpret_cast<const float4*>(x + idx + 4);
        __align__(16) __half2 h[4];
        h[0] = __floats2half2_rn(f0.x, f0.y);
        h[1] = __floats2half2_rn(f0.z, f0.w);
        h[2] = __floats2half2_rn(f1.x, f1.y);
        h[3] = __floats2half2_rn(f1.z, f1.w);
        *reinterpret_cast<uint4*>(g_Xh + idx) = *reinterpret_cast<const uint4*>(h);
    } else if (bid < 13696) {
        const int r  = bid - 8192;            // 0..5503
        const int bx = r & 15;                // qrow block: 16 x 32 qrows
        const int by = r >> 4;                // n block: 344 x 32 n
        const int tx = threadIdx.x & 31;      // n_local
        const int ty = threadIdx.x >> 5;      // 0..7 (4 qrows each)
        const int n  = by * 32 + tx;
        const int g  = bx * 2 + (ty >> 2);

        const int z = (qzeros[g * (OUT_F / 8) + (n >> 3)] >> ((n & 7) * 4)) & 15;
        const __half2 s2  = __half2half2(load_scale(scales, g * OUT_F + n));
        const __half2 mz2 = __half2half2(__float2half((float)(1024 + z)));

        #pragma unroll
        for (int i = 0; i < 4; i++) {
            const int qrl = ty * 4 + i;
            const uint32_t q = (uint32_t)qweight[(size_t)(bx * 32 + qrl) * OUT_F + n];
            uint32_t t0 = ( q         & 0x000F000Fu) | 0x64006400u;
            uint32_t t1 = ((q >> 4)   & 0x000F000Fu) | 0x64006400u;
            uint32_t t2 = ((q >> 8)   & 0x000F000Fu) | 0x64006400u;
            uint32_t t3 = ((q >> 12)  & 0x000F000Fu) | 0x64006400u;
            __half2 p0 = __hmul2(__hsub2(*(__half2*)&t0, mz2), s2);
            __half2 p1 = __hmul2(__hsub2(*(__half2*)&t1, mz2), s2);
            __half2 p2 = __hmul2(__hsub2(*(__half2*)&t2, mz2), s2);
            __half2 p3 = __hmul2(__hsub2(*(__half2*)&t3, mz2), s2);
            uint32_t u0 = *(uint32_t*)&p0, u1 = *(uint32_t*)&p1;
            uint32_t u2 = *(uint32_t*)&p2, u3 = *(uint32_t*)&p3;
            uint4 o;
            o.x = __byte_perm(u0, u1, 0x5410);
            o.y = __byte_perm(u2, u3, 0x5410);
            o.z = __byte_perm(u0, u1, 0x7632);
            o.w = __byte_perm(u2, u3, 0x7632);
            ts[qrl * 33 + tx] = o;
        }
        __syncthreads();

        uint4* W = reinterpret_cast<uint4*>(g_Wh);
        #pragma unroll
        for (int j = 0; j < 4; j++) {
            const int nl = ty + j * 8;
            const int ng = by * 32 + nl;
            W[(size_t)ng * (IN_F / 8) + bx * 32 + tx] = ts[tx * 33 + nl];
        }
    } else {
        // ---- zero path: out[m][10624..11007], 393216 float4 total ----
        int idx = (bid - 13696) * 256 + threadIdx.x;   // 0..393215
        int m  = idx / 96;
        int c4 = idx % 96;
        float4 zv = make_float4(0.f, 0.f, 0.f, 0.f);
        *reinterpret_cast<float4*>(out + (size_t)m * OUT_F + 10624 + c4 * 4) = zv;
    }
}

// ---------------------------------------------------------------------------
// HGEMM (mma.sync): CTA 128x128, 4 warps (2m x 2n), warp tile 64x64, BK=64,
// 3-stage cp.async, 96KB smem -> 2 CTAs/SM, SW128 swizzle.
// Grid 2840: bids [0,2664) = full-K tiles 0..2663 (exactly 9 waves);
// bids [2664,2840) = 176 split-K CTAs covering tiles 2664..2751 (2 k-halves
// each, combined via atomicAdd onto the zeroed region; k-half 0 adds bias).
// ---------------------------------------------------------------------------
constexpr int BM  = 128;
constexpr int BN  = 128;
constexpr int BK  = 64;                   // halves
constexpr int STG = 3;
constexpr int A_BYTES = BM * BK * 2;      // 16KB
constexpr int B_BYTES = BN * BK * 2;      // 16KB
constexpr int STAGE_BYTES = A_BYTES + B_BYTES;          // 32KB
constexpr int GEMM_SMEM = STG * STAGE_BYTES;            // 96KB

__device__ __forceinline__ uint32_t smem_u32(const void* p) {
    uint32_t a;
    asm("{ .reg .u64 t; cvta.to.shared.u64 t, %1; cvt.u32.u64 %0, t; }"
        : "=r"(a) : "l"(p));
    return a;
}
// byte offset of (row, 16B chunk ch in 0..7) within a tile: 128B rows, SW128
__device__ __forceinline__ uint32_t sw_byte(int row, int ch) {
    return (uint32_t)((row << 7) + ((ch ^ (row & 7)) << 4));
}

__global__ __launch_bounds__(128, 2) void gemm_kernel(
    const float* __restrict__ bias, float* __restrict__ out)
{
    extern __shared__ char smem[];
    const uint32_t sbase = smem_u32(smem);

    const int tid  = threadIdx.x;
    const int lane = tid & 31;
    const int warp = tid >> 5;        // 0..3
    const int warp_m = warp & 1;
    const int warp_n = warp >> 1;

    // tile / k-range assignment
    int tile, kbase, nchunks, khalf, is_split;
    if (blockIdx.x < 2664) {
        tile = blockIdx.x; kbase = 0; nchunks = 64; khalf = 0; is_split = 0;
    } else {
        int s = blockIdx.x - 2664;            // 0..175
        tile = 2664 + (s >> 1);
        khalf = s & 1;
        kbase = khalf * 32;
        nchunks = 32;
        is_split = 1;
    }
    const int pid_m = tile & 31;              // m fastest (L2 reuse of A)
    const int pid_n = tile >> 5;
    const int m_base = pid_m * BM;
    const int n_base = pid_n * BN;

    float acc[4][8][4];
    #pragma unroll
    for (int mi = 0; mi < 4; mi++)
        #pragma unroll
        for (int ni = 0; ni < 8; ni++)
            #pragma unroll
            for (int r = 0; r < 4; r++) acc[mi][ni][r] = 0.f;

    // producer: 2048 16B copies (A 1024, B 1024), 16 per thread
    auto produce = [&](int cc) {
        const uint32_t st = sbase + (cc % STG) * STAGE_BYTES;
        const int k0 = (kbase + cc) * BK;
        #pragma unroll
        for (int i = 0; i < 16; i++) {
            int id = tid + i * 128;           // 0..2047
            if (id < 1024) {
                int row = id >> 3, ch = id & 7;
                const __half* src = g_Xh + (size_t)(m_base + row) * IN_F + k0 + ch * 8;
                asm volatile("cp.async.cg.shared.global [%0], [%1], 16;\n"
                             :: "r"(st + sw_byte(row, ch)), "l"(src));
            } else {
                int idb = id - 1024;
                int row = idb >> 3, ch = idb & 7;
                const __half* src = g_Wh + (size_t)(n_base + row) * IN_F + k0 + ch * 8;
                asm volatile("cp.async.cg.shared.global [%0], [%1], 16;\n"
                             :: "r"(st + A_BYTES + sw_byte(row, ch)), "l"(src));
            }
        }
        asm volatile("cp.async.commit_group;\n");
    };

    auto compute = [&](int cc) {
        const uint32_t st = sbase + (cc % STG) * STAGE_BYTES;
        #pragma unroll
        for (int ks = 0; ks < 4; ks++) {      // 4 k16 sub-steps
            const int kc = ks * 2;
            uint32_t a[4][4], b[8][2];
            #pragma unroll
            for (int mi = 0; mi < 4; mi++) {
                int row = warp_m * 64 + mi * 16 + (lane & 15);
                int ch  = kc + (lane >> 4);
                uint32_t addr = st + sw_byte(row, ch);
                asm volatile(
                    "ldmatrix.sync.aligned.m8n8.x4.shared.b16 {%0,%1,%2,%3}, [%4];"
                    : "=r"(a[mi][0]), "=r"(a[mi][1]), "=r"(a[mi][2]), "=r"(a[mi][3])
                    : "r"(addr));
            }
            #pragma unroll
            for (int nt = 0; nt < 4; nt++) {
                int row = warp_n * 64 + nt * 16 + ((lane >> 4) << 3) + (lane & 7);
                int ch  = kc + ((lane >> 3) & 1);
                uint32_t addr = st + A_BYTES + sw_byte(row, ch);
                asm volatile(
                    "ldmatrix.sync.aligned.m8n8.x4.shared.b16 {%0,%1,%2,%3}, [%4];"
                    : "=r"(b[2*nt][0]), "=r"(b[2*nt][1]),
                      "=r"(b[2*nt+1][0]), "=r"(b[2*nt+1][1])
                    : "r"(addr));
            }
            #pragma unroll
            for (int mi = 0; mi < 4; mi++)
                #pragma unroll
                for (int ni = 0; ni < 8; ni++)
                    asm volatile(
                        "mma.sync.aligned.m16n8k16.row.col.f32.f16.f16.f32 "
                        "{%0,%1,%2,%3}, {%4,%5,%6,%7}, {%8,%9}, {%0,%1,%2,%3};"
                        : "+f"(acc[mi][ni][0]), "+f"(acc[mi][ni][1]),
                          "+f"(acc[mi][ni][2]), "+f"(acc[mi][ni][3])
                        : "r"(a[mi][0]), "r"(a[mi][1]), "r"(a[mi][2]), "r"(a[mi][3]),
                          "r"(b[ni][0]), "r"(b[ni][1]));
        }
    };

    // prologue: stages 0,1 in flight
    produce(0);
    produce(1);

    for (int c = 0; c < nchunks; c++) {
        asm volatile("cp.async.wait_group 1;\n");        // group c complete
        __syncthreads();                                 // compute(c-1) done
        if (c + 2 < nchunks) produce(c + 2);             // stage (c+2)%3 == (c-1)%3
        else asm volatile("cp.async.commit_group;\n");   // uniform group count
        compute(c);
    }

    // epilogue
    if (!is_split) {
        #pragma unroll
        for (int mi = 0; mi < 4; mi++) {
            int row0 = m_base + warp_m * 64 + mi * 16 + (lane >> 2);
            #pragma unroll
            for (int ni = 0; ni < 8; ni++) {
                int col = n_base + warp_n * 64 + ni * 8 + ((lane & 3) << 1);
                float b0 = bias[col], b1 = bias[col + 1];
                float2 v0 = make_float2(acc[mi][ni][0] + b0, acc[mi][ni][1] + b1);
                float2 v1 = make_float2(acc[mi][ni][2] + b0, acc[mi][ni][3] + b1);
                *reinterpret_cast<float2*>(out + (size_t)row0 * OUT_F + col)       = v0;
                *reinterpret_cast<float2*>(out + (size_t)(row0 + 8) * OUT_F + col) = v1;
            }
        }
    } else {
        // split-K: accumulate into zeroed region; k-half 0 contributes bias.
        // Exactly two IEEE adds per element onto 0.0 -> order-independent bits.
        #pragma unroll
        for (int mi = 0; mi < 4; mi++) {
            int row0 = m_base + warp_m * 64 + mi * 16 + (lane >> 2);
            #pragma unroll
            for (int ni = 0; ni < 8; ni++) {
                int col = n_base + warp_n * 64 + ni * 8 + ((lane & 3) << 1);
                float b0 = (khalf == 0) ? bias[col]     : 0.f;
                float b1 = (khalf == 0) ? bias[col + 1] : 0.f;
                atomicAdd(out + (size_t)row0 * OUT_F + col,           acc[mi][ni][0] + b0);
                atomicAdd(out + (size_t)row0 * OUT_F + col + 1,       acc[mi][ni][1] + b1);
                atomicAdd(out + (size_t)(row0 + 8) * OUT_F + col,     acc[mi][ni][2] + b0);
                atomicAdd(out + (size_t)(row0 + 8) * OUT_F + col + 1, acc[mi][ni][3] + b1);
            }
        }
    }
}

// ---------------------------------------------------------------------------
extern "C" void kernel_launch(void* const* d_in, const int* in_sizes, int n_in,
                              void* d_out, int out_size)
{
    const void *p_x = nullptr, *p_qw = nullptr, *p_qz = nullptr,
               *p_sc = nullptr, *p_b = nullptr;
    for (int i = 0; i < n_in; i++) {
        switch (in_sizes[i]) {
            case M_ROWS * IN_F:        p_x  = d_in[i]; break;
            case (IN_F / 8) * OUT_F:   p_qw = d_in[i]; break;
            case NGROUPS * (OUT_F/8):  p_qz = d_in[i]; break;
            case NGROUPS * OUT_F:      p_sc = d_in[i]; break;
            case OUT_F:                p_b  = d_in[i]; break;
        }
    }

    probe_init<<<1, 1>>>();
    probe_kernel<<<(176128 + 255) / 256, 256>>>(p_sc);

    // fused pre-pass: cvt (8192) + dequant (5504) + tail zero-fill (1536)
    prep_kernel<<<8192 + 5504 + 1536, 256>>>((const float*)p_x,
                                             (const int*)p_qw, (const int*)p_qz,
                                             p_sc, (float*)d_out);

    // Not stream-ordered; safe and deterministic on every call (incl. capture).
    cudaFuncSetAttribute(gemm_kernel,
                         cudaFuncAttributeMaxDynamicSharedMemorySize, GEMM_SMEM);

    // grid: 2664 full-K CTAs (9 exact waves) + 176 split-K tail CTAs
    gemm_kernel<<<2664 + 176, 128, GEMM_SMEM>>>((const float*)p_b, (float*)d_out);
}

// round 17
// speedup vs baseline: 1.0665x; 1.0001x over previous
#include <cuda_runtime.h>
#include <cuda_fp16.h>
#include <cuda_bf16.h>
#include <cstdint>

// Problem constants
#define IN_F    4096
#define OUT_F   11008
#define M_ROWS  4096
#define NGROUPS 32

// Scratch (no cudaMalloc allowed)
__device__ __half g_Xh[(size_t)M_ROWS * IN_F];    // fp16 x
__device__ __half g_Wh[(size_t)OUT_F * IN_F];     // fp16 dequant W, [n][k]
__device__ float  g_part[3u * 88u * 16384u];      // split-K tail partials (17MB)
__device__ int    g_bad_f16;
__device__ int    g_bad_bf16;

// ---------------------------------------------------------------------------
// scales dtype probe (unchanged from passing rounds)
// ---------------------------------------------------------------------------
__global__ void probe_init() { g_bad_f16 = 0; g_bad_bf16 = 0; }

__global__ void probe_kernel(const void* __restrict__ scales) {
    int i = blockIdx.x * blockDim.x + threadIdx.x;
    if (i >= 176128) return;
    float vf = __half2float(((const __half*)scales)[i]);
    if (!(vf >= 0.0f && vf < 1.0f)) atomicExch(&g_bad_f16, 1);
    float vb = __bfloat162float(((const __nv_bfloat16*)scales)[i]);
    if (!(vb >= 0.0f && vb < 1.0f)) atomicExch(&g_bad_bf16, 1);
}

__device__ __forceinline__ __half load_scale(const void* scales, int idx) {
    if (!g_bad_f16)       return ((const __half*)scales)[idx];
    else if (!g_bad_bf16) return __float2half(
                              __bfloat162float(((const __nv_bfloat16*)scales)[idx]));
    else                  return __float2half(((const float*)scales)[idx]);
}

// ---------------------------------------------------------------------------
// Fused pre-pass (R14-validated):
//   blocks [0, 8192):      x fp32 -> g_Xh fp16
//   blocks [8192, 13696):  dequant qweight -> g_Wh (coalesced transpose)
// ---------------------------------------------------------------------------
__global__ __launch_bounds__(256) void prep_kernel(
    const float* __restrict__ x,
    const int* __restrict__ qweight, const int* __restrict__ qzeros,
    const void* __restrict__ scales)
{
    __shared__ __align__(16) uint4 ts[32 * 33];   // [qrow_local][n_local], pad 33

    const int bid = blockIdx.x;
    if (bid < 8192) {
        int idx = (bid * 256 + threadIdx.x) * 8;
        float4 f0 = *reinterpret_cast<const float4*>(x + idx);
        float4 f1 = *reinterpret_cast<const float4*>(x + idx + 4);
        __align__(16) __half2 h[4];
        h[0] = __floats2half2_rn(f0.x, f0.y);
        h[1] = __floats2half2_rn(f0.z, f0.w);
        h[2] = __floats2half2_rn(f1.x, f1.y);
        h[3] = __floats2half2_rn(f1.z, f1.w);
        *reinterpret_cast<uint4*>(g_Xh + idx) = *reinterpret_cast<const uint4*>(h);
    } else {
        const int r  = bid - 8192;            // 0..5503
        const int bx = r & 15;                // qrow block: 16 x 32 qrows
        const int by = r >> 4;                // n block: 344 x 32 n
        const int tx = threadIdx.x & 31;      // n_local
        const int ty = threadIdx.x >> 5;      // 0..7 (4 qrows each)
        const int n  = by * 32 + tx;
        const int g  = bx * 2 + (ty >> 2);

        const int z = (qzeros[g * (OUT_F / 8) + (n >> 3)] >> ((n & 7) * 4)) & 15;
        const __half2 s2  = __half2half2(load_scale(scales, g * OUT_F + n));
        const __half2 mz2 = __half2half2(__float2half((float)(1024 + z)));

        #pragma unroll
        for (int i = 0; i < 4; i++) {
            const int qrl = ty * 4 + i;
            const uint32_t q = (uint32_t)qweight[(size_t)(bx * 32 + qrl) * OUT_F + n];
            uint32_t t0 = ( q         & 0x000F000Fu) | 0x64006400u;
            uint32_t t1 = ((q >> 4)   & 0x000F000Fu) | 0x64006400u;
            uint32_t t2 = ((q >> 8)   & 0x000F000Fu) | 0x64006400u;
            uint32_t t3 = ((q >> 12)  & 0x000F000Fu) | 0x64006400u;
            __half2 p0 = __hmul2(__hsub2(*(__half2*)&t0, mz2), s2);
            __half2 p1 = __hmul2(__hsub2(*(__half2*)&t1, mz2), s2);
            __half2 p2 = __hmul2(__hsub2(*(__half2*)&t2, mz2), s2);
            __half2 p3 = __hmul2(__hsub2(*(__half2*)&t3, mz2), s2);
            uint32_t u0 = *(uint32_t*)&p0, u1 = *(uint32_t*)&p1;
            uint32_t u2 = *(uint32_t*)&p2, u3 = *(uint32_t*)&p3;
            uint4 o;
            o.x = __byte_perm(u0, u1, 0x5410);
            o.y = __byte_perm(u2, u3, 0x5410);
            o.z = __byte_perm(u0, u1, 0x7632);
            o.w = __byte_perm(u2, u3, 0x7632);
            ts[qrl * 33 + tx] = o;
        }
        __syncthreads();

        uint4* W = reinterpret_cast<uint4*>(g_Wh);
        #pragma unroll
        for (int j = 0; j < 4; j++) {
            const int nl = ty + j * 8;
            const int ng = by * 32 + nl;
            W[(size_t)ng * (IN_F / 8) + bx * 32 + tx] = ts[tx * 33 + nl];
        }
    }
}

// ---------------------------------------------------------------------------
// HGEMM: CTA 128x128, 4 warps (2m x 2n), warp 64x64, BK=64, 3-stage
// cp.async, 96KB smem -> 2 CTAs/SM, SW128 swizzle.
// Grid 2928: bids [0,2664) = full-K tiles (9 exact waves);
// bids [2664,2928) = 264 split-K CTAs: tiles 2664..2751 x 3 k-parts
// (chunks 22/21/21). Split CTAs plain-store partials to g_part (disjoint
// slices, deterministic); combine_kernel sums them in fixed order.
// ---------------------------------------------------------------------------
constexpr int BM  = 128;
constexpr int BN  = 128;
constexpr int BK  = 64;                   // halves
constexpr int STG = 3;
constexpr int A_BYTES = BM * BK * 2;      // 16KB
constexpr int B_BYTES = BN * BK * 2;      // 16KB
constexpr int STAGE_BYTES = A_BYTES + B_BYTES;          // 32KB
constexpr int GEMM_SMEM = STG * STAGE_BYTES;            // 96KB

__device__ __forceinline__ uint32_t smem_u32(const void* p) {
    uint32_t a;
    asm("{ .reg .u64 t; cvta.to.shared.u64 t, %1; cvt.u32.u64 %0, t; }"
        : "=r"(a) : "l"(p));
    return a;
}
// byte offset of (row, 16B chunk ch in 0..7) within a tile: 128B rows, SW128
__device__ __forceinline__ uint32_t sw_byte(int row, int ch) {
    return (uint32_t)((row << 7) + ((ch ^ (row & 7)) << 4));
}

__global__ __launch_bounds__(128, 2) void gemm_kernel(
    const float* __restrict__ bias, float* __restrict__ out)
{
    extern __shared__ char smem[];
    const uint32_t sbase = smem_u32(smem);

    const int tid  = threadIdx.x;
    const int lane = tid & 31;
    const int warp = tid >> 5;        // 0..3
    const int warp_m = warp & 1;
    const int warp_n = warp >> 1;

    // tile / k-range assignment
    int tile, kbase, nchunks, tl, kpart, is_split;
    if (blockIdx.x < 2664) {
        tile = blockIdx.x; kbase = 0; nchunks = 64; tl = 0; kpart = 0; is_split = 0;
    } else {
        int s = blockIdx.x - 2664;            // 0..263
        tl    = s / 3;                        // tail tile 0..87
        kpart = s % 3;
        tile  = 2664 + tl;
        kbase   = (kpart == 0) ? 0  : (kpart == 1 ? 22 : 43);
        nchunks = (kpart == 0) ? 22 : 21;
        is_split = 1;
    }
    const int pid_m = tile & 31;              // m fastest (L2 reuse of A)
    const int pid_n = tile >> 5;
    const int m_base = pid_m * BM;
    const int n_base = pid_n * BN;

    float acc[4][8][4];
    #pragma unroll
    for (int mi = 0; mi < 4; mi++)
        #pragma unroll
        for (int ni = 0; ni < 8; ni++)
            #pragma unroll
            for (int r = 0; r < 4; r++) acc[mi][ni][r] = 0.f;

    // producer: 2048 16B copies (A 1024, B 1024), 16 per thread
    auto produce = [&](int cc) {
        const uint32_t st = sbase + (cc % STG) * STAGE_BYTES;
        const int k0 = (kbase + cc) * BK;
        #pragma unroll
        for (int i = 0; i < 16; i++) {
            int id = tid + i * 128;           // 0..2047
            if (id < 1024) {
                int row = id >> 3, ch = id & 7;
                const __half* src = g_Xh + (size_t)(m_base + row) * IN_F + k0 + ch * 8;
                asm volatile("cp.async.cg.shared.global [%0], [%1], 16;\n"
                             :: "r"(st + sw_byte(row, ch)), "l"(src));
            } else {
                int idb = id - 1024;
                int row = idb >> 3, ch = idb & 7;
                const __half* src = g_Wh + (size_t)(n_base + row) * IN_F + k0 + ch * 8;
                asm volatile("cp.async.cg.shared.global [%0], [%1], 16;\n"
                             :: "r"(st + A_BYTES + sw_byte(row, ch)), "l"(src));
            }
        }
        asm volatile("cp.async.commit_group;\n");
    };

    auto compute = [&](int cc) {
        const uint32_t st = sbase + (cc % STG) * STAGE_BYTES;
        #pragma unroll
        for (int ks = 0; ks < 4; ks++) {      // 4 k16 sub-steps
            const int kc = ks * 2;
            uint32_t a[4][4], b[8][2];
            #pragma unroll
            for (int mi = 0; mi < 4; mi++) {
                int row = warp_m * 64 + mi * 16 + (lane & 15);
                int ch  = kc + (lane >> 4);
                uint32_t addr = st + sw_byte(row, ch);
                asm volatile(
                    "ldmatrix.sync.aligned.m8n8.x4.shared.b16 {%0,%1,%2,%3}, [%4];"
                    : "=r"(a[mi][0]), "=r"(a[mi][1]), "=r"(a[mi][2]), "=r"(a[mi][3])
                    : "r"(addr));
            }
            #pragma unroll
            for (int nt = 0; nt < 4; nt++) {
                int row = warp_n * 64 + nt * 16 + ((lane >> 4) << 3) + (lane & 7);
                int ch  = kc + ((lane >> 3) & 1);
                uint32_t addr = st + A_BYTES + sw_byte(row, ch);
                asm volatile(
                    "ldmatrix.sync.aligned.m8n8.x4.shared.b16 {%0,%1,%2,%3}, [%4];"
                    : "=r"(b[2*nt][0]), "=r"(b[2*nt][1]),
                      "=r"(b[2*nt+1][0]), "=r"(b[2*nt+1][1])
                    : "r"(addr));
            }
            #pragma unroll
            for (int mi = 0; mi < 4; mi++)
                #pragma unroll
                for (int ni = 0; ni < 8; ni++)
                    asm volatile(
                        "mma.sync.aligned.m16n8k16.row.col.f32.f16.f16.f32 "
                        "{%0,%1,%2,%3}, {%4,%5,%6,%7}, {%8,%9}, {%0,%1,%2,%3};"
                        : "+f"(acc[mi][ni][0]), "+f"(acc[mi][ni][1]),
                          "+f"(acc[mi][ni][2]), "+f"(acc[mi][ni][3])
                        : "r"(a[mi][0]), "r"(a[mi][1]), "r"(a[mi][2]), "r"(a[mi][3]),
                          "r"(b[ni][0]), "r"(b[ni][1]));
        }
    };

    // prologue: stages 0,1 in flight
    produce(0);
    produce(1);

    for (int c = 0; c < nchunks; c++) {
        asm volatile("cp.async.wait_group 1;\n");        // group c complete
        __syncthreads();                                 // compute(c-1) done
        if (c + 2 < nchunks) produce(c + 2);             // stage (c+2)%3 == (c-1)%3
        else asm volatile("cp.async.commit_group;\n");   // uniform group count
        compute(c);
    }

    // epilogue
    if (!is_split) {
        #pragma unroll
        for (int mi = 0; mi < 4; mi++) {
            int row0 = m_base + warp_m * 64 + mi * 16 + (lane >> 2);
            #pragma unroll
            for (int ni = 0; ni < 8; ni++) {
                int col = n_base + warp_n * 64 + ni * 8 + ((lane & 3) << 1);
                float b0 = bias[col], b1 = bias[col + 1];
                float2 v0 = make_float2(acc[mi][ni][0] + b0, acc[mi][ni][1] + b1);
                float2 v1 = make_float2(acc[mi][ni][2] + b0, acc[mi][ni][3] + b1);
                *reinterpret_cast<float2*>(out + (size_t)row0 * OUT_F + col)       = v0;
                *reinterpret_cast<float2*>(out + (size_t)(row0 + 8) * OUT_F + col) = v1;
            }
        }
    } else {
        // plain-store partials to a disjoint scratch slice (deterministic)
        float* P = g_part + ((size_t)kpart * 88 + tl) * 16384;
        #pragma unroll
        for (int mi = 0; mi < 4; mi++) {
            int rl = warp_m * 64 + mi * 16 + (lane >> 2);
            #pragma unroll
            for (int ni = 0; ni < 8; ni++) {
                int cl = warp_n * 64 + ni * 8 + ((lane & 3) << 1);
                *reinterpret_cast<float2*>(P + rl * 128 + cl) =
                    make_float2(acc[mi][ni][0], acc[mi][ni][1]);
                *reinterpret_cast<float2*>(P + (rl + 8) * 128 + cl) =
                    make_float2(acc[mi][ni][2], acc[mi][ni][3]);
            }
        }
    }
}

// ---------------------------------------------------------------------------
// Combiner: out = part0 + part1 + part2 + bias (fixed order -> deterministic)
// 360448 float4 = 1408 blocks x 256 threads.
// ---------------------------------------------------------------------------
__global__ __launch_bounds__(256) void combine_kernel(
    const float* __restrict__ bias, float* __restrict__ out)
{
    const int p  = blockIdx.x * 256 + threadIdx.x;   // 0..360447
    const int tl = p >> 12;          // tail tile 0..87
    const int q  = p & 4095;
    const int row = q >> 5;          // 0..127
    const int c4  = (q & 31) * 4;    // 0..124
    const int tile = 2664 + tl;
    const int m = (tile & 31) * 128 + row;
    const int n = (tile >> 5) * 128 + c4;

    const size_t off = (size_t)tl * 16384 + row * 128 + c4;
    float4 a = *reinterpret_cast<const float4*>(g_part + off);
    float4 b = *reinterpret_cast<const float4*>(g_part + 88u * 16384u + off);
    float4 c = *reinterpret_cast<const float4*>(g_part + 2u * 88u * 16384u + off);
    float4 bv = *reinterpret_cast<const float4*>(bias + n);
    float4 r;
    r.x = ((a.x + b.x) + c.x) + bv.x;
    r.y = ((a.y + b.y) + c.y) + bv.y;
    r.z = ((a.z + b.z) + c.z) + bv.z;
    r.w = ((a.w + b.w) + c.w) + bv.w;
    *reinterpret_cast<float4*>(out + (size_t)m * OUT_F + n) = r;
}

// ---------------------------------------------------------------------------
extern "C" void kernel_launch(void* const* d_in, const int* in_sizes, int n_in,
                              void* d_out, int out_size)
{
    const void *p_x = nullptr, *p_qw = nullptr, *p_qz = nullptr,
               *p_sc = nullptr, *p_b = nullptr;
    for (int i = 0; i < n_in; i++) {
        switch (in_sizes[i]) {
            case M_ROWS * IN_F:        p_x  = d_in[i]; break;
            case (IN_F / 8) * OUT_F:   p_qw = d_in[i]; break;
            case NGROUPS * (OUT_F/8):  p_qz = d_in[i]; break;
            case NGROUPS * OUT_F:      p_sc = d_in[i]; break;
            case OUT_F:                p_b  = d_in[i]; break;
        }
    }

    probe_init<<<1, 1>>>();
    probe_kernel<<<(176128 + 255) / 256, 256>>>(p_sc);

    // fused pre-pass: cvt (8192) + dequant (5504)
    prep_kernel<<<8192 + 5504, 256>>>((const float*)p_x,
                                      (const int*)p_qw, (const int*)p_qz, p_sc);

    // Not stream-ordered; safe and deterministic on every call (incl. capture).
    cudaFuncSetAttribute(gemm_kernel,
                         cudaFuncAttributeMaxDynamicSharedMemorySize, GEMM_SMEM);

    // grid: 2664 full-K CTAs (9 exact waves) + 264 split-K tail CTAs (3 parts)
    gemm_kernel<<<2664 + 264, 128, GEMM_SMEM>>>((const float*)p_b, (float*)d_out);

    // deterministic tail combine: partials summed in fixed order + bias
    combine_kernel<<<1408, 256>>>((const float*)p_b, (float*)d_out);
}